// round 3
// baseline (speedup 1.0000x reference)
#include <cuda_runtime.h>
#include <math_constants.h>

#define KFEAT   64
#define NNODES  100000
#define ONSET_F 0.8f
#define CUTOFF_F 1.0f

// Scratch accumulator (no cudaMalloc allowed): 100000*64 floats = 25.6 MB
__device__ float g_agg[NNODES * KFEAT];

// ---------------------------------------------------------------------------
// Kernel 0: zero the accumulator (float4 stores)
// ---------------------------------------------------------------------------
__global__ void zero_agg_kernel(int n4) {
    int i = blockIdx.x * blockDim.x + threadIdx.x;
    if (i < n4) {
        reinterpret_cast<float4*>(g_agg)[i] = make_float4(0.f, 0.f, 0.f, 0.f);
    }
}

// ---------------------------------------------------------------------------
// Kernel 1: edge message + scatter.
// 16 threads per edge; thread q handles features [4q, 4q+4) (one float4).
// rbf_k = exp(-gamma*(d - mu_k)^2), mu_k = k/63, gamma = 64.
// msg = h[src] * rbf * fcut ; accumulated into g_agg[dst] via RED.128.
// Groups whose entire 4-wide RBF bundle is < ~2e-9 are skipped BEFORE any
// further loads/math (contribution is 5 orders below the 1e-3 gate).
// ---------------------------------------------------------------------------
__global__ void edge_kernel(const float* __restrict__ h,
                            const float* __restrict__ dist,
                            const int*   __restrict__ src,
                            const int*   __restrict__ dst,
                            int E) {
    long long t = (long long)blockIdx.x * blockDim.x + threadIdx.x;
    int e = (int)(t >> 4);
    if (e >= E) return;
    int q = (int)(t & 15);           // which float4 of the 64-feature row

    float d = __ldg(&dist[e]);

    const float gamma = (float)KFEAT / (CUTOFF_F - 0.0f);   // 64
    const float dmu   = CUTOFF_F / (float)(KFEAT - 1);      // 1/63

    float mu = (float)(q * 4) * dmu;

    // Distance from d to the nearest mu in this 4-wide group.
    float gap = fmaxf(fmaxf(mu - d, d - (mu + 3.0f * dmu)), 0.0f);
    // exp(-64*gap^2) < 2e-9  <=>  gap > 0.5477. d >= 1.0 => fcut == 0.
    if (gap > 0.5477f || d >= CUTOFF_F) return;

    // smooth cutoff (only for surviving threads)
    float fc = 1.0f;
    if (d > ONSET_F) {
        float x = (d - ONSET_F) * (1.0f / (CUTOFF_F - ONSET_F));
        fc = 0.5f * (__cosf(CUDART_PI_F * x) + 1.0f);
    }

    float t0 = d - mu;
    float t1 = d - (mu + dmu);
    float t2 = d - (mu + 2.0f * dmu);
    float t3 = d - (mu + 3.0f * dmu);

    float w0 = __expf(-gamma * t0 * t0) * fc;
    float w1 = __expf(-gamma * t1 * t1) * fc;
    float w2 = __expf(-gamma * t2 * t2) * fc;
    float w3 = __expf(-gamma * t3 * t3) * fc;

    int s  = __ldg(&src[e]);
    int dd = __ldg(&dst[e]);

    float4 hv = __ldg(&reinterpret_cast<const float4*>(h)[(long long)s * (KFEAT / 4) + q]);

    float4 m = make_float4(hv.x * w0, hv.y * w1, hv.z * w2, hv.w * w3);

    float4* dstp = &reinterpret_cast<float4*>(g_agg)[(long long)dd * (KFEAT / 4) + q];
#if defined(__CUDA_ARCH__) && (__CUDA_ARCH__ >= 900)
    atomicAdd(dstp, m);
#else
    float* fp = reinterpret_cast<float*>(dstp);
    atomicAdd(fp + 0, m.x);
    atomicAdd(fp + 1, m.y);
    atomicAdd(fp + 2, m.z);
    atomicAdd(fp + 3, m.w);
#endif
}

// ---------------------------------------------------------------------------
// Kernel 2: per-node MLP. One warp per node.
// hid = softplus(agg @ W1 + b1); out = hid @ W2 + b2.
// W1/W2/b in shared memory; activations broadcast via __shfl_sync.
// Lane holds columns {lane, lane+32}.
// ---------------------------------------------------------------------------
__device__ __forceinline__ float softplus_f(float x) {
    // logaddexp(x, 0) = max(x,0) + log1p(exp(-|x|))  (matches jax.nn.softplus)
    return fmaxf(x, 0.0f) + log1pf(expf(-fabsf(x)));
}

__global__ __launch_bounds__(256) void mlp_kernel(const float* __restrict__ W1,
                                                  const float* __restrict__ b1,
                                                  const float* __restrict__ W2,
                                                  const float* __restrict__ b2,
                                                  float* __restrict__ out,
                                                  int N) {
    __shared__ float sW1[KFEAT * KFEAT];
    __shared__ float sW2[KFEAT * KFEAT];
    __shared__ float sb1[KFEAT];
    __shared__ float sb2[KFEAT];

    for (int i = threadIdx.x; i < KFEAT * KFEAT; i += blockDim.x) {
        sW1[i] = W1[i];
        sW2[i] = W2[i];
    }
    if (threadIdx.x < KFEAT) {
        sb1[threadIdx.x] = b1[threadIdx.x];
        sb2[threadIdx.x] = b2[threadIdx.x];
    }
    __syncthreads();

    const unsigned FULL = 0xffffffffu;
    int lane   = threadIdx.x & 31;
    int warp   = (blockIdx.x * blockDim.x + threadIdx.x) >> 5;
    int nwarps = (gridDim.x * blockDim.x) >> 5;

    for (int n = warp; n < N; n += nwarps) {
        const float* arow = &g_agg[(long long)n * KFEAT];
        float a0 = arow[lane];
        float a1 = arow[lane + 32];

        // ---- layer 1 ----
        float acc0 = sb1[lane];
        float acc1 = sb1[lane + 32];
#pragma unroll
        for (int k = 0; k < 32; k++) {
            float a = __shfl_sync(FULL, a0, k);
            acc0 = fmaf(a, sW1[k * KFEAT + lane],      acc0);
            acc1 = fmaf(a, sW1[k * KFEAT + lane + 32], acc1);
        }
#pragma unroll
        for (int k = 0; k < 32; k++) {
            float a = __shfl_sync(FULL, a1, k);
            acc0 = fmaf(a, sW1[(k + 32) * KFEAT + lane],      acc0);
            acc1 = fmaf(a, sW1[(k + 32) * KFEAT + lane + 32], acc1);
        }

        float h0 = softplus_f(acc0);
        float h1 = softplus_f(acc1);

        // ---- layer 2 ----
        float o0 = sb2[lane];
        float o1 = sb2[lane + 32];
#pragma unroll
        for (int k = 0; k < 32; k++) {
            float a = __shfl_sync(FULL, h0, k);
            o0 = fmaf(a, sW2[k * KFEAT + lane],      o0);
            o1 = fmaf(a, sW2[k * KFEAT + lane + 32], o1);
        }
#pragma unroll
        for (int k = 0; k < 32; k++) {
            float a = __shfl_sync(FULL, h1, k);
            o0 = fmaf(a, sW2[(k + 32) * KFEAT + lane],      o0);
            o1 = fmaf(a, sW2[(k + 32) * KFEAT + lane + 32], o1);
        }

        out[(long long)n * KFEAT + lane]      = o0;
        out[(long long)n * KFEAT + lane + 32] = o1;
    }
}

// ---------------------------------------------------------------------------
// Inputs (metadata order): h, dist, W1, b1, W2, b2, src_idx, dst_idx
// ---------------------------------------------------------------------------
extern "C" void kernel_launch(void* const* d_in, const int* in_sizes, int n_in,
                              void* d_out, int out_size) {
    const float* h    = (const float*)d_in[0];
    const float* dist = (const float*)d_in[1];
    const float* W1   = (const float*)d_in[2];
    const float* b1   = (const float*)d_in[3];
    const float* W2   = (const float*)d_in[4];
    const float* b2   = (const float*)d_in[5];
    const int*   src  = (const int*)d_in[6];
    const int*   dst  = (const int*)d_in[7];
    float* out = (float*)d_out;

    int E = in_sizes[1];            // n_edges
    int N = in_sizes[0] / KFEAT;    // n_nodes

    // 1) zero accumulator
    int n4 = N * (KFEAT / 4);
    zero_agg_kernel<<<(n4 + 255) / 256, 256>>>(n4);

    // 2) edge scatter: 16 threads per edge
    long long tot = (long long)E * 16;
    int blocks = (int)((tot + 255) / 256);
    edge_kernel<<<blocks, 256>>>(h, dist, src, dst, E);

    // 3) MLP: warp per node, persistent-ish grid
    mlp_kernel<<<592, 256>>>(W1, b1, W2, b2, out, N);
}

// round 4
// speedup vs baseline: 1.3681x; 1.3681x over previous
#include <cuda_runtime.h>
#include <math_constants.h>

#define KFEAT   64
#define NNODES  100000
#define ONSET_F 0.8f
#define CUTOFF_F 1.0f

// Scratch accumulator (no cudaMalloc allowed): 100000*64 floats = 25.6 MB
__device__ float g_agg[NNODES * KFEAT];

// ---------------------------------------------------------------------------
// Kernel 0: zero the accumulator (float4 stores)
// ---------------------------------------------------------------------------
__global__ void zero_agg_kernel(int n4) {
    int i = blockIdx.x * blockDim.x + threadIdx.x;
    if (i < n4) {
        reinterpret_cast<float4*>(g_agg)[i] = make_float4(0.f, 0.f, 0.f, 0.f);
    }
}

// ---------------------------------------------------------------------------
// Kernel 1: edge message + scatter.
// 16 threads per edge; thread q handles features [4q, 4q+4) (one float4).
// rbf_k = exp(-gamma*(d - mu_k)^2), mu_k = k/63, gamma = 64.
// Skip a 4-wide group when its max rbf < 1.24e-5 (gap > 0.42): removes the
// gather AND the atomic; accumulated error ~5e-5 vs the 1e-3 gate.
// ---------------------------------------------------------------------------
__global__ void edge_kernel(const float* __restrict__ h,
                            const float* __restrict__ dist,
                            const int*   __restrict__ src,
                            const int*   __restrict__ dst,
                            int E) {
    long long t = (long long)blockIdx.x * blockDim.x + threadIdx.x;
    int e = (int)(t >> 4);
    if (e >= E) return;
    int q = (int)(t & 15);           // which float4 of the 64-feature row

    float d = __ldg(&dist[e]);

    const float gamma = (float)KFEAT / (CUTOFF_F - 0.0f);   // 64
    const float dmu   = CUTOFF_F / (float)(KFEAT - 1);      // 1/63

    float mu = (float)(q * 4) * dmu;

    // Distance from d to the nearest mu in this 4-wide group.
    float gap = fmaxf(fmaxf(mu - d, d - (mu + 3.0f * dmu)), 0.0f);
    // exp(-64*gap^2) < 1.24e-5  <=>  gap > 0.42. d >= 1.0 => fcut == 0.
    if (gap > 0.42f || d >= CUTOFF_F) return;

    // smooth cutoff (only for surviving threads)
    float fc = 1.0f;
    if (d > ONSET_F) {
        float x = (d - ONSET_F) * (1.0f / (CUTOFF_F - ONSET_F));
        fc = 0.5f * (__cosf(CUDART_PI_F * x) + 1.0f);
    }

    float t0 = d - mu;
    float t1 = d - (mu + dmu);
    float t2 = d - (mu + 2.0f * dmu);
    float t3 = d - (mu + 3.0f * dmu);

    float w0 = __expf(-gamma * t0 * t0) * fc;
    float w1 = __expf(-gamma * t1 * t1) * fc;
    float w2 = __expf(-gamma * t2 * t2) * fc;
    float w3 = __expf(-gamma * t3 * t3) * fc;

    int s  = __ldg(&src[e]);
    int dd = __ldg(&dst[e]);

    float4 hv = __ldg(&reinterpret_cast<const float4*>(h)[(long long)s * (KFEAT / 4) + q]);

    float4 m = make_float4(hv.x * w0, hv.y * w1, hv.z * w2, hv.w * w3);

    float4* dstp = &reinterpret_cast<float4*>(g_agg)[(long long)dd * (KFEAT / 4) + q];
#if defined(__CUDA_ARCH__) && (__CUDA_ARCH__ >= 900)
    atomicAdd(dstp, m);
#else
    float* fp = reinterpret_cast<float*>(dstp);
    atomicAdd(fp + 0, m.x);
    atomicAdd(fp + 1, m.y);
    atomicAdd(fp + 2, m.z);
    atomicAdd(fp + 3, m.w);
#endif
}

// ---------------------------------------------------------------------------
// Kernel 2: MLP as a register-blocked tiled SGEMM.
// Block = 64 nodes. 256 threads, each owns a 4x4 output block.
// smem: W1 (16KB) + W2 (16KB) + A-tile transposed (16KB) = 48KB exactly.
// Per k-step per thread: 2x LDS.128 + 16 FFMA -> FMA-bound (~45us floor),
// vs. the previous warp-per-node version which issued one LDS per FMA.
// ---------------------------------------------------------------------------
__device__ __forceinline__ float softplus_f(float x) {
    // logaddexp(x, 0) = max(x,0) + log1p(exp(-|x|))  (matches jax.nn.softplus)
    return fmaxf(x, 0.0f) + log1pf(expf(-fabsf(x)));
}

__global__ __launch_bounds__(256) void mlp_gemm_kernel(const float* __restrict__ W1g,
                                                       const float* __restrict__ b1,
                                                       const float* __restrict__ W2g,
                                                       const float* __restrict__ b2,
                                                       float* __restrict__ out,
                                                       int N) {
    __shared__ float sW1[KFEAT * KFEAT];   // W1[k][c], row-major
    __shared__ float sW2[KFEAT * KFEAT];   // W2[c][o], row-major
    __shared__ float sA[KFEAT * KFEAT];    // A^T: sA[k][n] (layer1), then hid^T: sA[c][n] (layer2)

    int tid = threadIdx.x;
    int tx  = tid & 15;   // output-column group: cols [4*tx, 4*tx+4)
    int ty  = tid >> 4;   // node group: nodes [4*ty, 4*ty+4)
    int base = blockIdx.x * 64;

    // Stage weights
    for (int i = tid; i < KFEAT * KFEAT; i += 256) {
        sW1[i] = W1g[i];
        sW2[i] = W2g[i];
    }

    // Stage A transposed: coalesced float4 reads from g_agg, staggered STS
    // (jj = (j+kq)&3 cuts the stride-64 transpose conflict from 8-way to 4-way).
#pragma unroll
    for (int it = 0; it < 4; it++) {
        int fidx = tid + it * 256;    // 0..1023
        int n  = fidx >> 4;           // 0..63 local node
        int kq = fidx & 15;           // float4 index within the row
        int node = base + n;
        float4 v = make_float4(0.f, 0.f, 0.f, 0.f);
        if (node < N) v = __ldg(&reinterpret_cast<const float4*>(g_agg)[(long long)node * 16 + kq]);
        float vv[4] = {v.x, v.y, v.z, v.w};
#pragma unroll
        for (int j = 0; j < 4; j++) {
            int jj = (j + kq) & 3;
            sA[(4 * kq + jj) * 64 + n] = vv[jj];
        }
    }
    __syncthreads();

    int n0 = ty * 4, c0 = tx * 4;

    float acc[4][4];
    {
        float4 bv = __ldg(&reinterpret_cast<const float4*>(b1)[tx]);
        float bb[4] = {bv.x, bv.y, bv.z, bv.w};
#pragma unroll
        for (int i = 0; i < 4; i++)
#pragma unroll
            for (int j = 0; j < 4; j++) acc[i][j] = bb[j];
    }

    // ---- layer 1: acc[i][j] += A[n0+i][k] * W1[k][c0+j] ----
#pragma unroll 4
    for (int k = 0; k < KFEAT; k++) {
        float4 a = *reinterpret_cast<const float4*>(&sA[k * 64 + n0]);
        float4 w = *reinterpret_cast<const float4*>(&sW1[k * 64 + c0]);
        acc[0][0] = fmaf(a.x, w.x, acc[0][0]);
        acc[0][1] = fmaf(a.x, w.y, acc[0][1]);
        acc[0][2] = fmaf(a.x, w.z, acc[0][2]);
        acc[0][3] = fmaf(a.x, w.w, acc[0][3]);
        acc[1][0] = fmaf(a.y, w.x, acc[1][0]);
        acc[1][1] = fmaf(a.y, w.y, acc[1][1]);
        acc[1][2] = fmaf(a.y, w.z, acc[1][2]);
        acc[1][3] = fmaf(a.y, w.w, acc[1][3]);
        acc[2][0] = fmaf(a.z, w.x, acc[2][0]);
        acc[2][1] = fmaf(a.z, w.y, acc[2][1]);
        acc[2][2] = fmaf(a.z, w.z, acc[2][2]);
        acc[2][3] = fmaf(a.z, w.w, acc[2][3]);
        acc[3][0] = fmaf(a.w, w.x, acc[3][0]);
        acc[3][1] = fmaf(a.w, w.y, acc[3][1]);
        acc[3][2] = fmaf(a.w, w.z, acc[3][2]);
        acc[3][3] = fmaf(a.w, w.w, acc[3][3]);
    }
    __syncthreads();   // everyone done reading sA before it becomes hid^T

    // softplus, write hid transposed into sA: sA[c][n]
    // i staggered by tx to spread the stride-64 STS across banks (16-way -> 4-way)
#pragma unroll
    for (int j = 0; j < 4; j++) {
#pragma unroll
        for (int ii = 0; ii < 4; ii++) {
            int i = (ii + tx) & 3;
            sA[(c0 + j) * 64 + (n0 + i)] = softplus_f(acc[i][j]);
        }
    }
    __syncthreads();

    // ---- layer 2: acc[i][j] = b2[c0+j] + sum_c hid[n0+i][c] * W2[c][c0+j] ----
    {
        float4 bv = __ldg(&reinterpret_cast<const float4*>(b2)[tx]);
        float bb[4] = {bv.x, bv.y, bv.z, bv.w};
#pragma unroll
        for (int i = 0; i < 4; i++)
#pragma unroll
            for (int j = 0; j < 4; j++) acc[i][j] = bb[j];
    }

#pragma unroll 4
    for (int c = 0; c < KFEAT; c++) {
        float4 a = *reinterpret_cast<const float4*>(&sA[c * 64 + n0]);
        float4 w = *reinterpret_cast<const float4*>(&sW2[c * 64 + c0]);
        acc[0][0] = fmaf(a.x, w.x, acc[0][0]);
        acc[0][1] = fmaf(a.x, w.y, acc[0][1]);
        acc[0][2] = fmaf(a.x, w.z, acc[0][2]);
        acc[0][3] = fmaf(a.x, w.w, acc[0][3]);
        acc[1][0] = fmaf(a.y, w.x, acc[1][0]);
        acc[1][1] = fmaf(a.y, w.y, acc[1][1]);
        acc[1][2] = fmaf(a.y, w.z, acc[1][2]);
        acc[1][3] = fmaf(a.y, w.w, acc[1][3]);
        acc[2][0] = fmaf(a.z, w.x, acc[2][0]);
        acc[2][1] = fmaf(a.z, w.y, acc[2][1]);
        acc[2][2] = fmaf(a.z, w.z, acc[2][2]);
        acc[2][3] = fmaf(a.z, w.w, acc[2][3]);
        acc[3][0] = fmaf(a.w, w.x, acc[3][0]);
        acc[3][1] = fmaf(a.w, w.y, acc[3][1]);
        acc[3][2] = fmaf(a.w, w.z, acc[3][2]);
        acc[3][3] = fmaf(a.w, w.w, acc[3][3]);
    }

    // Store: float4 per node row
#pragma unroll
    for (int i = 0; i < 4; i++) {
        int node = base + n0 + i;
        if (node < N) {
            float4 o = make_float4(acc[i][0], acc[i][1], acc[i][2], acc[i][3]);
            reinterpret_cast<float4*>(out)[(long long)node * 16 + tx] = o;
        }
    }
}

// ---------------------------------------------------------------------------
// Inputs (metadata order): h, dist, W1, b1, W2, b2, src_idx, dst_idx
// ---------------------------------------------------------------------------
extern "C" void kernel_launch(void* const* d_in, const int* in_sizes, int n_in,
                              void* d_out, int out_size) {
    const float* h    = (const float*)d_in[0];
    const float* dist = (const float*)d_in[1];
    const float* W1   = (const float*)d_in[2];
    const float* b1   = (const float*)d_in[3];
    const float* W2   = (const float*)d_in[4];
    const float* b2   = (const float*)d_in[5];
    const int*   src  = (const int*)d_in[6];
    const int*   dst  = (const int*)d_in[7];
    float* out = (float*)d_out;

    int E = in_sizes[1];            // n_edges
    int N = in_sizes[0] / KFEAT;    // n_nodes

    // 1) zero accumulator
    int n4 = N * (KFEAT / 4);
    zero_agg_kernel<<<(n4 + 255) / 256, 256>>>(n4);

    // 2) edge scatter: 16 threads per edge
    long long tot = (long long)E * 16;
    int blocks = (int)((tot + 255) / 256);
    edge_kernel<<<blocks, 256>>>(h, dist, src, dst, E);

    // 3) MLP: tiled SGEMM, 64 nodes per block
    int mblocks = (N + 63) / 64;
    mlp_gemm_kernel<<<mblocks, 256>>>(W1, b1, W2, b2, out, N);
}

// round 5
// speedup vs baseline: 1.4515x; 1.0609x over previous
#include <cuda_runtime.h>
#include <math_constants.h>

#define KFEAT   64
#define NNODES  100000
#define CAP     64          // per-node edge-bin capacity (Poisson(16) max ~50)
#define ONSET_F 0.8f
#define CUTOFF_F 1.0f

// Scratch (no cudaMalloc allowed):
__device__ float g_agg[NNODES * KFEAT];    // 25.6 MB accumulator
__device__ int   g_cnt[NNODES];            // per-node edge count
__device__ int   g_bin[NNODES * CAP];      // 25.6 MB binned edge ids

// ---------------------------------------------------------------------------
// Kernel 0: zero accumulator + counts
// ---------------------------------------------------------------------------
__global__ void zero_kernel(int n4, int N) {
    int i = blockIdx.x * blockDim.x + threadIdx.x;
    if (i < n4) {
        reinterpret_cast<float4*>(g_agg)[i] = make_float4(0.f, 0.f, 0.f, 0.f);
    }
    if (i < N) g_cnt[i] = 0;
}

// ---------------------------------------------------------------------------
// Kernel 1: bin edges by dst. 1 thread per edge, int atomic only.
// Overflow fallback (should never fire for Poisson(16) vs CAP=64): do the
// full message with float4 atomics directly — correctness preserved.
// ---------------------------------------------------------------------------
__global__ void bin_kernel(const float* __restrict__ h,
                           const float* __restrict__ dist,
                           const int*   __restrict__ src,
                           const int*   __restrict__ dst,
                           int E) {
    int e = blockIdx.x * blockDim.x + threadIdx.x;
    if (e >= E) return;
    int dd = __ldg(&dst[e]);
    int pos = atomicAdd(&g_cnt[dd], 1);
    if (pos < CAP) {
        g_bin[dd * CAP + pos] = e;
    } else {
        // rare/never: direct atomic accumulation
        float d = __ldg(&dist[e]);
        if (d >= CUTOFF_F) return;
        float fc = 1.0f;
        if (d > ONSET_F) {
            float x = (d - ONSET_F) * (1.0f / (CUTOFF_F - ONSET_F));
            fc = 0.5f * (__cosf(CUDART_PI_F * x) + 1.0f);
        }
        const float gamma = 64.0f;
        const float dmu = 1.0f / 63.0f;
        int s = __ldg(&src[e]);
        for (int q = 0; q < 16; q++) {
            float mu = (float)(q * 4) * dmu;
            float t0 = d - mu;
            float t1 = d - (mu + dmu);
            float t2 = d - (mu + 2.0f * dmu);
            float t3 = d - (mu + 3.0f * dmu);
            float4 hv = __ldg(&reinterpret_cast<const float4*>(h)[(long long)s * 16 + q]);
            float4 m = make_float4(hv.x * __expf(-gamma * t0 * t0) * fc,
                                   hv.y * __expf(-gamma * t1 * t1) * fc,
                                   hv.z * __expf(-gamma * t2 * t2) * fc,
                                   hv.w * __expf(-gamma * t3 * t3) * fc);
#if defined(__CUDA_ARCH__) && (__CUDA_ARCH__ >= 900)
            atomicAdd(&reinterpret_cast<float4*>(g_agg)[(long long)dd * 16 + q], m);
#else
            float* fp = &g_agg[((long long)dd * 16 + q) * 4];
            atomicAdd(fp + 0, m.x); atomicAdd(fp + 1, m.y);
            atomicAdd(fp + 2, m.z); atomicAdd(fp + 3, m.w);
#endif
        }
    }
}

// ---------------------------------------------------------------------------
// Kernel 2: gather-accumulate. 16 threads per dst node; thread q owns
// features [4q,4q+4). Loops the node's binned edges with metadata prefetch;
// register accumulation; single (non-atomic) RMW store at the end.
// 4-wide RBF groups with max rbf < 1.24e-5 (gap > 0.42) are skipped.
// ---------------------------------------------------------------------------
__global__ void gather_kernel(const float* __restrict__ h,
                              const float* __restrict__ dist,
                              const int*   __restrict__ src,
                              int N) {
    int t = blockIdx.x * blockDim.x + threadIdx.x;
    int n = t >> 4;
    if (n >= N) return;
    int q = t & 15;

    const float gamma = 64.0f;
    const float dmu   = 1.0f / 63.0f;
    float mu = (float)(q * 4) * dmu;

    int deg = min(g_cnt[n], CAP);

    float a0 = 0.f, a1 = 0.f, a2 = 0.f, a3 = 0.f;

    if (deg > 0) {
        const int* bp = &g_bin[n * CAP];
        // prefetch first edge's metadata (16-lane broadcast loads)
        int   e = __ldg(&bp[0]);
        float d = __ldg(&dist[e]);
        int   s = __ldg(&src[e]);

        for (int j = 0; j < deg; j++) {
            int   e_n = 0; float d_n = 0.f; int s_n = 0;
            if (j + 1 < deg) {
                e_n = __ldg(&bp[j + 1]);
                d_n = __ldg(&dist[e_n]);
                s_n = __ldg(&src[e_n]);
            }

            // group skip: nearest-mu gap; fcut==0 for d>=1
            float gap = fmaxf(fmaxf(mu - d, d - (mu + 3.0f * dmu)), 0.0f);
            if (gap <= 0.42f && d < CUTOFF_F) {
                float fc = 1.0f;
                if (d > ONSET_F) {
                    float x = (d - ONSET_F) * (1.0f / (CUTOFF_F - ONSET_F));
                    fc = 0.5f * (__cosf(CUDART_PI_F * x) + 1.0f);
                }
                float t0 = d - mu;
                float t1 = d - (mu + dmu);
                float t2 = d - (mu + 2.0f * dmu);
                float t3 = d - (mu + 3.0f * dmu);

                float4 hv = __ldg(&reinterpret_cast<const float4*>(h)[(long long)s * 16 + q]);

                a0 = fmaf(hv.x, __expf(-gamma * t0 * t0) * fc, a0);
                a1 = fmaf(hv.y, __expf(-gamma * t1 * t1) * fc, a1);
                a2 = fmaf(hv.z, __expf(-gamma * t2 * t2) * fc, a2);
                a3 = fmaf(hv.w, __expf(-gamma * t3 * t3) * fc, a3);
            }
            e = e_n; d = d_n; s = s_n;
        }
    }

    // single writer per (n,q) — plus any (rare) fallback contributions already
    // atomically deposited by bin_kernel, so read-modify-write.
    float4* p = &reinterpret_cast<float4*>(g_agg)[(long long)n * 16 + q];
    float4 old = *p;
    *p = make_float4(old.x + a0, old.y + a1, old.z + a2, old.w + a3);
}

// ---------------------------------------------------------------------------
// Kernel 3: MLP as register-blocked tiled SGEMM (unchanged from R4).
// Block = 64 nodes, 256 threads, 4x4 outputs per thread. smem = 48KB.
// ---------------------------------------------------------------------------
__device__ __forceinline__ float softplus_f(float x) {
    return fmaxf(x, 0.0f) + log1pf(expf(-fabsf(x)));
}

__global__ __launch_bounds__(256) void mlp_gemm_kernel(const float* __restrict__ W1g,
                                                       const float* __restrict__ b1,
                                                       const float* __restrict__ W2g,
                                                       const float* __restrict__ b2,
                                                       float* __restrict__ out,
                                                       int N) {
    __shared__ float sW1[KFEAT * KFEAT];
    __shared__ float sW2[KFEAT * KFEAT];
    __shared__ float sA[KFEAT * KFEAT];

    int tid = threadIdx.x;
    int tx  = tid & 15;
    int ty  = tid >> 4;
    int base = blockIdx.x * 64;

    for (int i = tid; i < KFEAT * KFEAT; i += 256) {
        sW1[i] = W1g[i];
        sW2[i] = W2g[i];
    }

#pragma unroll
    for (int it = 0; it < 4; it++) {
        int fidx = tid + it * 256;
        int n  = fidx >> 4;
        int kq = fidx & 15;
        int node = base + n;
        float4 v = make_float4(0.f, 0.f, 0.f, 0.f);
        if (node < N) v = __ldg(&reinterpret_cast<const float4*>(g_agg)[(long long)node * 16 + kq]);
        float vv[4] = {v.x, v.y, v.z, v.w};
#pragma unroll
        for (int j = 0; j < 4; j++) {
            int jj = (j + kq) & 3;
            sA[(4 * kq + jj) * 64 + n] = vv[jj];
        }
    }
    __syncthreads();

    int n0 = ty * 4, c0 = tx * 4;

    float acc[4][4];
    {
        float4 bv = __ldg(&reinterpret_cast<const float4*>(b1)[tx]);
        float bb[4] = {bv.x, bv.y, bv.z, bv.w};
#pragma unroll
        for (int i = 0; i < 4; i++)
#pragma unroll
            for (int j = 0; j < 4; j++) acc[i][j] = bb[j];
    }

#pragma unroll 4
    for (int k = 0; k < KFEAT; k++) {
        float4 a = *reinterpret_cast<const float4*>(&sA[k * 64 + n0]);
        float4 w = *reinterpret_cast<const float4*>(&sW1[k * 64 + c0]);
        acc[0][0] = fmaf(a.x, w.x, acc[0][0]); acc[0][1] = fmaf(a.x, w.y, acc[0][1]);
        acc[0][2] = fmaf(a.x, w.z, acc[0][2]); acc[0][3] = fmaf(a.x, w.w, acc[0][3]);
        acc[1][0] = fmaf(a.y, w.x, acc[1][0]); acc[1][1] = fmaf(a.y, w.y, acc[1][1]);
        acc[1][2] = fmaf(a.y, w.z, acc[1][2]); acc[1][3] = fmaf(a.y, w.w, acc[1][3]);
        acc[2][0] = fmaf(a.z, w.x, acc[2][0]); acc[2][1] = fmaf(a.z, w.y, acc[2][1]);
        acc[2][2] = fmaf(a.z, w.z, acc[2][2]); acc[2][3] = fmaf(a.z, w.w, acc[2][3]);
        acc[3][0] = fmaf(a.w, w.x, acc[3][0]); acc[3][1] = fmaf(a.w, w.y, acc[3][1]);
        acc[3][2] = fmaf(a.w, w.z, acc[3][2]); acc[3][3] = fmaf(a.w, w.w, acc[3][3]);
    }
    __syncthreads();

#pragma unroll
    for (int j = 0; j < 4; j++) {
#pragma unroll
        for (int ii = 0; ii < 4; ii++) {
            int i = (ii + tx) & 3;
            sA[(c0 + j) * 64 + (n0 + i)] = softplus_f(acc[i][j]);
        }
    }
    __syncthreads();

    {
        float4 bv = __ldg(&reinterpret_cast<const float4*>(b2)[tx]);
        float bb[4] = {bv.x, bv.y, bv.z, bv.w};
#pragma unroll
        for (int i = 0; i < 4; i++)
#pragma unroll
            for (int j = 0; j < 4; j++) acc[i][j] = bb[j];
    }

#pragma unroll 4
    for (int c = 0; c < KFEAT; c++) {
        float4 a = *reinterpret_cast<const float4*>(&sA[c * 64 + n0]);
        float4 w = *reinterpret_cast<const float4*>(&sW2[c * 64 + c0]);
        acc[0][0] = fmaf(a.x, w.x, acc[0][0]); acc[0][1] = fmaf(a.x, w.y, acc[0][1]);
        acc[0][2] = fmaf(a.x, w.z, acc[0][2]); acc[0][3] = fmaf(a.x, w.w, acc[0][3]);
        acc[1][0] = fmaf(a.y, w.x, acc[1][0]); acc[1][1] = fmaf(a.y, w.y, acc[1][1]);
        acc[1][2] = fmaf(a.y, w.z, acc[1][2]); acc[1][3] = fmaf(a.y, w.w, acc[1][3]);
        acc[2][0] = fmaf(a.z, w.x, acc[2][0]); acc[2][1] = fmaf(a.z, w.y, acc[2][1]);
        acc[2][2] = fmaf(a.z, w.z, acc[2][2]); acc[2][3] = fmaf(a.z, w.w, acc[2][3]);
        acc[3][0] = fmaf(a.w, w.x, acc[3][0]); acc[3][1] = fmaf(a.w, w.y, acc[3][1]);
        acc[3][2] = fmaf(a.w, w.z, acc[3][2]); acc[3][3] = fmaf(a.w, w.w, acc[3][3]);
    }

#pragma unroll
    for (int i = 0; i < 4; i++) {
        int node = base + n0 + i;
        if (node < N) {
            float4 o = make_float4(acc[i][0], acc[i][1], acc[i][2], acc[i][3]);
            reinterpret_cast<float4*>(out)[(long long)node * 16 + tx] = o;
        }
    }
}

// ---------------------------------------------------------------------------
// Inputs (metadata order): h, dist, W1, b1, W2, b2, src_idx, dst_idx
// ---------------------------------------------------------------------------
extern "C" void kernel_launch(void* const* d_in, const int* in_sizes, int n_in,
                              void* d_out, int out_size) {
    const float* h    = (const float*)d_in[0];
    const float* dist = (const float*)d_in[1];
    const float* W1   = (const float*)d_in[2];
    const float* b1   = (const float*)d_in[3];
    const float* W2   = (const float*)d_in[4];
    const float* b2   = (const float*)d_in[5];
    const int*   src  = (const int*)d_in[6];
    const int*   dst  = (const int*)d_in[7];
    float* out = (float*)d_out;

    int E = in_sizes[1];            // n_edges
    int N = in_sizes[0] / KFEAT;    // n_nodes

    // 1) zero accumulator + counts
    int n4 = N * (KFEAT / 4);
    zero_kernel<<<(n4 + 255) / 256, 256>>>(n4, N);

    // 2) bin edges by dst (int atomics only)
    bin_kernel<<<(E + 255) / 256, 256>>>(h, dist, src, dst, E);

    // 3) gather-accumulate per node (no float atomics)
    int gt = N * 16;
    gather_kernel<<<(gt + 255) / 256, 256>>>(h, dist, src, N);

    // 4) MLP: tiled SGEMM, 64 nodes per block
    int mblocks = (N + 63) / 64;
    mlp_gemm_kernel<<<mblocks, 256>>>(W1, b1, W2, b2, out, N);
}

// round 7
// speedup vs baseline: 1.6280x; 1.1216x over previous
#include <cuda_runtime.h>
#include <math_constants.h>

#define KFEAT   64
#define NNODES  100000
#define CAP     64          // per-node edge-bin capacity (Poisson(16), max deg ~50)
#define ONSET_F 0.8f
#define CUTOFF_F 1.0f

// Scratch (no cudaMalloc allowed):
__device__ float g_agg[NNODES * KFEAT];    // 25.6 MB accumulator
__device__ int   g_cnt[NNODES];            // per-node edge count
__device__ int2  g_bin[NNODES * CAP];      // 51.2 MB packed (dist_bits, src) records

// ---------------------------------------------------------------------------
// Kernel 0: zero accumulator + counts (agg must be zero for the rare
// overflow-fallback atomics to compose with gather's RMW).
// ---------------------------------------------------------------------------
__global__ void zero_kernel(int n4, int N) {
    int i = blockIdx.x * blockDim.x + threadIdx.x;
    if (i < n4) {
        reinterpret_cast<float4*>(g_agg)[i] = make_float4(0.f, 0.f, 0.f, 0.f);
    }
    if (i < N) g_cnt[i] = 0;
}

// ---------------------------------------------------------------------------
// Kernel 1: bin edges by dst, storing packed (dist, src) records so the
// gather loop has a 1-deep dependent chain. Edges with d >= 1.0 carry an
// exactly-zero message (fcut = 0) and are dropped here.
// Overflow fallback (P ~ 0 for Poisson(16) vs CAP=64): direct float4 atomics.
// ---------------------------------------------------------------------------
__global__ void bin_kernel(const float* __restrict__ h,
                           const float* __restrict__ dist,
                           const int*   __restrict__ src,
                           const int*   __restrict__ dst,
                           int E) {
    int e = blockIdx.x * blockDim.x + threadIdx.x;
    if (e >= E) return;
    float d = __ldg(&dist[e]);
    if (d >= CUTOFF_F) return;           // exact skip: message is identically 0
    int dd = __ldg(&dst[e]);
    int s  = __ldg(&src[e]);
    int pos = atomicAdd(&g_cnt[dd], 1);
    if (pos < CAP) {
        g_bin[dd * CAP + pos] = make_int2(__float_as_int(d), s);
    } else {
        // rare/never: direct atomic accumulation (correctness preserved)
        float fc = 1.0f;
        if (d > ONSET_F) {
            float x = (d - ONSET_F) * (1.0f / (CUTOFF_F - ONSET_F));
            fc = 0.5f * (__cosf(CUDART_PI_F * x) + 1.0f);
        }
        const float gamma = 64.0f;
        const float dmu = 1.0f / 63.0f;
        for (int q = 0; q < 16; q++) {
            float mu = (float)(q * 4) * dmu;
            float t0 = d - mu;
            float t1 = d - (mu + dmu);
            float t2 = d - (mu + 2.0f * dmu);
            float t3 = d - (mu + 3.0f * dmu);
            float4 hv = __ldg(&reinterpret_cast<const float4*>(h)[(long long)s * 16 + q]);
            float4 m = make_float4(hv.x * __expf(-gamma * t0 * t0) * fc,
                                   hv.y * __expf(-gamma * t1 * t1) * fc,
                                   hv.z * __expf(-gamma * t2 * t2) * fc,
                                   hv.w * __expf(-gamma * t3 * t3) * fc);
#if defined(__CUDA_ARCH__) && (__CUDA_ARCH__ >= 900)
            atomicAdd(&reinterpret_cast<float4*>(g_agg)[(long long)dd * 16 + q], m);
#else
            float* fp = &g_agg[((long long)dd * 16 + q) * 4];
            atomicAdd(fp + 0, m.x); atomicAdd(fp + 1, m.y);
            atomicAdd(fp + 2, m.z); atomicAdd(fp + 3, m.w);
#endif
        }
    }
}

// ---------------------------------------------------------------------------
// Kernel 2: gather-accumulate. 16 threads per dst node; thread q owns
// features [4q,4q+4). Per edge: one 8B broadcast record load -> one dependent
// h float4 load (depth-1 prefetch hides most of it). Register accumulation;
// single RMW store. Groups with max rbf < 1.24e-5 (gap > 0.42) are skipped.
// ---------------------------------------------------------------------------
__global__ void gather_kernel(const float* __restrict__ h, int N) {
    int t = blockIdx.x * blockDim.x + threadIdx.x;
    int n = t >> 4;
    if (n >= N) return;
    int q = t & 15;

    const float gamma = 64.0f;
    const float dmu   = 1.0f / 63.0f;
    float mu = (float)(q * 4) * dmu;

    int deg = min(g_cnt[n], CAP);

    float a0 = 0.f, a1 = 0.f, a2 = 0.f, a3 = 0.f;

    if (deg > 0) {
        const int2* bp = &g_bin[n * CAP];
        int2 r = __ldg(&bp[0]);          // broadcast across the 16-lane group

        for (int j = 0; j < deg; j++) {
            int2 r_n = make_int2(0, 0);
            if (j + 1 < deg) r_n = __ldg(&bp[j + 1]);

            float d = __int_as_float(r.x);
            int   s = r.y;

            // group skip: nearest-mu gap (d < 1 guaranteed by bin_kernel)
            float gap = fmaxf(fmaxf(mu - d, d - (mu + 3.0f * dmu)), 0.0f);
            if (gap <= 0.42f) {
                float fc = 1.0f;
                if (d > ONSET_F) {
                    float x = (d - ONSET_F) * (1.0f / (CUTOFF_F - ONSET_F));
                    fc = 0.5f * (__cosf(CUDART_PI_F * x) + 1.0f);
                }
                float t0 = d - mu;
                float t1 = d - (mu + dmu);
                float t2 = d - (mu + 2.0f * dmu);
                float t3 = d - (mu + 3.0f * dmu);

                float4 hv = __ldg(&reinterpret_cast<const float4*>(h)[(long long)s * 16 + q]);

                a0 = fmaf(hv.x, __expf(-gamma * t0 * t0) * fc, a0);
                a1 = fmaf(hv.y, __expf(-gamma * t1 * t1) * fc, a1);
                a2 = fmaf(hv.z, __expf(-gamma * t2 * t2) * fc, a2);
                a3 = fmaf(hv.w, __expf(-gamma * t3 * t3) * fc, a3);
            }
            r = r_n;
        }
    }

    // single writer per (n,q); RMW to fold in (rare) fallback atomics.
    float4* p = &reinterpret_cast<float4*>(g_agg)[(long long)n * 16 + q];
    float4 old = *p;
    *p = make_float4(old.x + a0, old.y + a1, old.z + a2, old.w + a3);
}

// ---------------------------------------------------------------------------
// Kernel 3: MLP as register-blocked tiled SGEMM.
// Block = 64 nodes, 256 threads, 4x4 outputs per thread, smem = 48KB.
// __launch_bounds__(256, 4): cap regs at 64 -> 4 CTAs/SM (occ 23.8% -> ~50%).
// ---------------------------------------------------------------------------
__device__ __forceinline__ float softplus_f(float x) {
    return fmaxf(x, 0.0f) + log1pf(expf(-fabsf(x)));
}

__global__ __launch_bounds__(256, 4) void mlp_gemm_kernel(const float* __restrict__ W1g,
                                                          const float* __restrict__ b1,
                                                          const float* __restrict__ W2g,
                                                          const float* __restrict__ b2,
                                                          float* __restrict__ out,
                                                          int N) {
    __shared__ float sW1[KFEAT * KFEAT];
    __shared__ float sW2[KFEAT * KFEAT];
    __shared__ float sA[KFEAT * KFEAT];

    int tid = threadIdx.x;
    int tx  = tid & 15;
    int ty  = tid >> 4;
    int base = blockIdx.x * 64;

    for (int i = tid; i < KFEAT * KFEAT; i += 256) {
        sW1[i] = W1g[i];
        sW2[i] = W2g[i];
    }

#pragma unroll
    for (int it = 0; it < 4; it++) {
        int fidx = tid + it * 256;
        int n  = fidx >> 4;
        int kq = fidx & 15;
        int node = base + n;
        float4 v = make_float4(0.f, 0.f, 0.f, 0.f);
        if (node < N) v = __ldg(&reinterpret_cast<const float4*>(g_agg)[(long long)node * 16 + kq]);
        float vv[4] = {v.x, v.y, v.z, v.w};
#pragma unroll
        for (int j = 0; j < 4; j++) {
            int jj = (j + kq) & 3;
            sA[(4 * kq + jj) * 64 + n] = vv[jj];
        }
    }
    __syncthreads();

    int n0 = ty * 4, c0 = tx * 4;

    float acc[4][4];
    {
        float4 bv = __ldg(&reinterpret_cast<const float4*>(b1)[tx]);
#pragma unroll
        for (int i = 0; i < 4; i++) {
            acc[i][0] = bv.x; acc[i][1] = bv.y; acc[i][2] = bv.z; acc[i][3] = bv.w;
        }
    }

#pragma unroll 4
    for (int k = 0; k < KFEAT; k++) {
        float4 a = *reinterpret_cast<const float4*>(&sA[k * 64 + n0]);
        float4 w = *reinterpret_cast<const float4*>(&sW1[k * 64 + c0]);
        acc[0][0] = fmaf(a.x, w.x, acc[0][0]); acc[0][1] = fmaf(a.x, w.y, acc[0][1]);
        acc[0][2] = fmaf(a.x, w.z, acc[0][2]); acc[0][3] = fmaf(a.x, w.w, acc[0][3]);
        acc[1][0] = fmaf(a.y, w.x, acc[1][0]); acc[1][1] = fmaf(a.y, w.y, acc[1][1]);
        acc[1][2] = fmaf(a.y, w.z, acc[1][2]); acc[1][3] = fmaf(a.y, w.w, acc[1][3]);
        acc[2][0] = fmaf(a.z, w.x, acc[2][0]); acc[2][1] = fmaf(a.z, w.y, acc[2][1]);
        acc[2][2] = fmaf(a.z, w.z, acc[2][2]); acc[2][3] = fmaf(a.z, w.w, acc[2][3]);
        acc[3][0] = fmaf(a.w, w.x, acc[3][0]); acc[3][1] = fmaf(a.w, w.y, acc[3][1]);
        acc[3][2] = fmaf(a.w, w.z, acc[3][2]); acc[3][3] = fmaf(a.w, w.w, acc[3][3]);
    }
    __syncthreads();

#pragma unroll
    for (int j = 0; j < 4; j++) {
#pragma unroll
        for (int ii = 0; ii < 4; ii++) {
            int i = (ii + tx) & 3;
            sA[(c0 + j) * 64 + (n0 + i)] = softplus_f(acc[i][j]);
        }
    }
    __syncthreads();

    {
        float4 bv = __ldg(&reinterpret_cast<const float4*>(b2)[tx]);
#pragma unroll
        for (int i = 0; i < 4; i++) {
            acc[i][0] = bv.x; acc[i][1] = bv.y; acc[i][2] = bv.z; acc[i][3] = bv.w;
        }
    }

#pragma unroll 4
    for (int c = 0; c < KFEAT; c++) {
        float4 a = *reinterpret_cast<const float4*>(&sA[c * 64 + n0]);
        float4 w = *reinterpret_cast<const float4*>(&sW2[c * 64 + c0]);
        acc[0][0] = fmaf(a.x, w.x, acc[0][0]); acc[0][1] = fmaf(a.x, w.y, acc[0][1]);
        acc[0][2] = fmaf(a.x, w.z, acc[0][2]); acc[0][3] = fmaf(a.x, w.w, acc[0][3]);
        acc[1][0] = fmaf(a.y, w.x, acc[1][0]); acc[1][1] = fmaf(a.y, w.y, acc[1][1]);
        acc[1][2] = fmaf(a.y, w.z, acc[1][2]); acc[1][3] = fmaf(a.y, w.w, acc[1][3]);
        acc[2][0] = fmaf(a.z, w.x, acc[2][0]); acc[2][1] = fmaf(a.z, w.y, acc[2][1]);
        acc[2][2] = fmaf(a.z, w.z, acc[2][2]); acc[2][3] = fmaf(a.z, w.w, acc[2][3]);
        acc[3][0] = fmaf(a.w, w.x, acc[3][0]); acc[3][1] = fmaf(a.w, w.y, acc[3][1]);
        acc[3][2] = fmaf(a.w, w.z, acc[3][2]); acc[3][3] = fmaf(a.w, w.w, acc[3][3]);
    }

#pragma unroll
    for (int i = 0; i < 4; i++) {
        int node = base + n0 + i;
        if (node < N) {
            float4 o = make_float4(acc[i][0], acc[i][1], acc[i][2], acc[i][3]);
            reinterpret_cast<float4*>(out)[(long long)node * 16 + tx] = o;
        }
    }
}

// ---------------------------------------------------------------------------
// Inputs (metadata order): h, dist, W1, b1, W2, b2, src_idx, dst_idx
// ---------------------------------------------------------------------------
extern "C" void kernel_launch(void* const* d_in, const int* in_sizes, int n_in,
                              void* d_out, int out_size) {
    const float* h    = (const float*)d_in[0];
    const float* dist = (const float*)d_in[1];
    const float* W1   = (const float*)d_in[2];
    const float* b1   = (const float*)d_in[3];
    const float* W2   = (const float*)d_in[4];
    const float* b2   = (const float*)d_in[5];
    const int*   src  = (const int*)d_in[6];
    const int*   dst  = (const int*)d_in[7];
    float* out = (float*)d_out;

    int E = in_sizes[1];            // n_edges
    int N = in_sizes[0] / KFEAT;    // n_nodes

    // 1) zero accumulator + counts
    int n4 = N * (KFEAT / 4);
    zero_kernel<<<(n4 + 255) / 256, 256>>>(n4, N);

    // 2) bin edges by dst, packing (dist, src) records
    bin_kernel<<<(E + 255) / 256, 256>>>(h, dist, src, dst, E);

    // 3) gather-accumulate per node (no float atomics, 1-deep load chain)
    int gt = N * 16;
    gather_kernel<<<(gt + 255) / 256, 256>>>(h, N);

    // 4) MLP: tiled SGEMM, 64 nodes per block
    int mblocks = (N + 63) / 64;
    mlp_gemm_kernel<<<mblocks, 256>>>(W1, b1, W2, b2, out, N);
}

// round 13
// speedup vs baseline: 1.6502x; 1.0137x over previous
#include <cuda_runtime.h>
#include <math_constants.h>

#define KFEAT   64
#define NNODES  100000
#define CAP     64          // per-node edge-bin capacity (Poisson(16), max deg ~50)
#define OVF_CAP 1600000     // overflow list capacity = E (bulletproof)
#define ONSET_F 0.8f
#define CUTOFF_F 1.0f

// Scratch (no cudaMalloc allowed):
__device__ float g_agg[NNODES * KFEAT];    // 25.6 MB accumulator (NOT pre-zeroed)
__device__ int   g_cnt[NNODES];            // per-node edge count
__device__ int2  g_bin[NNODES * CAP];      // packed (dist_bits, src) records
__device__ int   g_ovf_cnt;                // overflow count
__device__ int   g_ovf[OVF_CAP];           // overflow edge ids

// ---- f32x2 helpers (sm_103a packed fp32 FMA; PTX-only) --------------------
__device__ __forceinline__ unsigned long long pack2(float lo, float hi) {
    unsigned long long r;
    asm("mov.b64 %0, {%1, %2};" : "=l"(r) : "r"(__float_as_uint(lo)), "r"(__float_as_uint(hi)));
    return r;
}
__device__ __forceinline__ unsigned long long rep2(float v) {
    unsigned long long r;
    asm("mov.b64 %0, {%1, %1};" : "=l"(r) : "r"(__float_as_uint(v)));
    return r;
}
__device__ __forceinline__ void fma2(unsigned long long& d, unsigned long long a, unsigned long long b) {
    asm("fma.rn.f32x2 %0, %1, %2, %0;" : "+l"(d) : "l"(a), "l"(b));
}
__device__ __forceinline__ void unpack2(unsigned long long v, float& lo, float& hi) {
    unsigned int l, h;
    asm("mov.b64 {%0, %1}, %2;" : "=r"(l), "=r"(h) : "l"(v));
    lo = __uint_as_float(l); hi = __uint_as_float(h);
}

// ---------------------------------------------------------------------------
// Kernel 0: zero counters only (g_agg is fully written by gather_kernel).
// ---------------------------------------------------------------------------
__global__ void zero_kernel(int N) {
    int i = blockIdx.x * blockDim.x + threadIdx.x;
    if (i < N) g_cnt[i] = 0;
    if (i == 0) g_ovf_cnt = 0;
}

// ---------------------------------------------------------------------------
// Kernel 1: bin edges by dst, storing packed (dist, src) records.
// d >= 1.0 edges carry an exactly-zero message (fcut=0) -> dropped.
// Overflow (deg > CAP, P ~ 0) goes to a list, processed after gather.
// ---------------------------------------------------------------------------
__global__ void bin_kernel(const float* __restrict__ dist,
                           const int*   __restrict__ src,
                           const int*   __restrict__ dst,
                           int E) {
    int e = blockIdx.x * blockDim.x + threadIdx.x;
    if (e >= E) return;
    float d = __ldg(&dist[e]);
    if (d >= CUTOFF_F) return;           // exact skip: message identically 0
    int dd = __ldg(&dst[e]);
    int pos = atomicAdd(&g_cnt[dd], 1);
    if (pos < CAP) {
        int s = __ldg(&src[e]);
        g_bin[dd * CAP + pos] = make_int2(__float_as_int(d), s);
    } else {
        int oi = atomicAdd(&g_ovf_cnt, 1);
        if (oi < OVF_CAP) g_ovf[oi] = e;
    }
}

// ---------------------------------------------------------------------------
// Kernel 2: gather-accumulate. 16 threads per dst node; thread q owns
// features [4q,4q+4). One 8B broadcast record load -> one dependent h float4
// load (depth-1 prefetch). Register accumulation; single PLAIN store (g_agg
// fully overwritten each launch). Groups with rbf < 1.24e-5 skipped.
// ---------------------------------------------------------------------------
__global__ void gather_kernel(const float* __restrict__ h, int N) {
    int t = blockIdx.x * blockDim.x + threadIdx.x;
    int n = t >> 4;
    if (n >= N) return;
    int q = t & 15;

    const float gamma = 64.0f;
    const float dmu   = 1.0f / 63.0f;
    float mu = (float)(q * 4) * dmu;

    int deg = min(g_cnt[n], CAP);

    float a0 = 0.f, a1 = 0.f, a2 = 0.f, a3 = 0.f;

    if (deg > 0) {
        const int2* bp = &g_bin[n * CAP];
        int2 r = __ldg(&bp[0]);          // broadcast across the 16-lane group

        for (int j = 0; j < deg; j++) {
            int2 r_n = make_int2(0, 0);
            if (j + 1 < deg) r_n = __ldg(&bp[j + 1]);

            float d = __int_as_float(r.x);
            int   s = r.y;

            float gap = fmaxf(fmaxf(mu - d, d - (mu + 3.0f * dmu)), 0.0f);
            if (gap <= 0.42f) {
                float fc = 1.0f;
                if (d > ONSET_F) {
                    float x = (d - ONSET_F) * (1.0f / (CUTOFF_F - ONSET_F));
                    fc = 0.5f * (__cosf(CUDART_PI_F * x) + 1.0f);
                }
                float t0 = d - mu;
                float t1 = d - (mu + dmu);
                float t2 = d - (mu + 2.0f * dmu);
                float t3 = d - (mu + 3.0f * dmu);

                float4 hv = __ldg(&reinterpret_cast<const float4*>(h)[(long long)s * 16 + q]);

                a0 = fmaf(hv.x, __expf(-gamma * t0 * t0) * fc, a0);
                a1 = fmaf(hv.y, __expf(-gamma * t1 * t1) * fc, a1);
                a2 = fmaf(hv.z, __expf(-gamma * t2 * t2) * fc, a2);
                a3 = fmaf(hv.w, __expf(-gamma * t3 * t3) * fc, a3);
            }
            r = r_n;
        }
    }

    reinterpret_cast<float4*>(g_agg)[(long long)n * 16 + q] =
        make_float4(a0, a1, a2, a3);
}

// ---------------------------------------------------------------------------
// Kernel 2b: overflow edges (normally zero work) — atomic adds AFTER gather.
// ---------------------------------------------------------------------------
__global__ void ovf_kernel(const float* __restrict__ h,
                           const float* __restrict__ dist,
                           const int*   __restrict__ src,
                           const int*   __restrict__ dst) {
    int tot = min(g_ovf_cnt, OVF_CAP);
    if (tot == 0) return;
    const float gamma = 64.0f;
    const float dmu = 1.0f / 63.0f;
    for (int t = blockIdx.x * blockDim.x + threadIdx.x; t < tot * 16;
         t += gridDim.x * blockDim.x) {
        int oi = t >> 4, q = t & 15;
        int e = g_ovf[oi];
        float d = __ldg(&dist[e]);
        int   s = __ldg(&src[e]);
        int   dd = __ldg(&dst[e]);
        float fc = 1.0f;
        if (d > ONSET_F) {
            float x = (d - ONSET_F) * (1.0f / (CUTOFF_F - ONSET_F));
            fc = 0.5f * (__cosf(CUDART_PI_F * x) + 1.0f);
        }
        float mu = (float)(q * 4) * dmu;
        float t0 = d - mu, t1 = d - (mu + dmu);
        float t2 = d - (mu + 2.0f * dmu), t3 = d - (mu + 3.0f * dmu);
        float4 hv = __ldg(&reinterpret_cast<const float4*>(h)[(long long)s * 16 + q]);
        float4 m = make_float4(hv.x * __expf(-gamma * t0 * t0) * fc,
                               hv.y * __expf(-gamma * t1 * t1) * fc,
                               hv.z * __expf(-gamma * t2 * t2) * fc,
                               hv.w * __expf(-gamma * t3 * t3) * fc);
#if defined(__CUDA_ARCH__) && (__CUDA_ARCH__ >= 900)
        atomicAdd(&reinterpret_cast<float4*>(g_agg)[(long long)dd * 16 + q], m);
#else
        float* fp = &g_agg[((long long)dd * 16 + q) * 4];
        atomicAdd(fp + 0, m.x); atomicAdd(fp + 1, m.y);
        atomicAdd(fp + 2, m.z); atomicAdd(fp + 3, m.w);
#endif
    }
}

// ---------------------------------------------------------------------------
// Kernel 3: MLP tiled SGEMM with packed f32x2 FMA (FFMA2).
// Block = 64 nodes, 256 threads, 4x4 outputs/thread (as 4x2 f32x2 pairs).
// sA padded to 68 floats/row to kill the stride-64 STS bank conflicts.
// Per k-step/thread: 2 LDS.128 + 4 MOV.b64 + 8 FFMA2 (was 16 FFMA).
// ---------------------------------------------------------------------------
__device__ __forceinline__ float softplus_f(float x) {
    return fmaxf(x, 0.0f) + log1pf(expf(-fabsf(x)));
}

#define APAD 68

__global__ __launch_bounds__(256, 4) void mlp_gemm_kernel(const float* __restrict__ W1g,
                                                          const float* __restrict__ b1,
                                                          const float* __restrict__ W2g,
                                                          const float* __restrict__ b2,
                                                          float* __restrict__ out,
                                                          int N) {
    __shared__ float sW1[KFEAT * KFEAT];
    __shared__ float sW2[KFEAT * KFEAT];
    __shared__ float sA[KFEAT * APAD];   // A^T then hid^T, padded rows

    int tid = threadIdx.x;
    int tx  = tid & 15;
    int ty  = tid >> 4;
    int base = blockIdx.x * 64;

    for (int i = tid; i < KFEAT * KFEAT; i += 256) {
        sW1[i] = W1g[i];
        sW2[i] = W2g[i];
    }

    // Stage A transposed: coalesced float4 LDG; STS into padded rows.
#pragma unroll
    for (int it = 0; it < 4; it++) {
        int fidx = tid + it * 256;
        int n  = fidx >> 4;           // local node 0..63
        int kq = fidx & 15;           // float4 index in row
        int node = base + n;
        float4 v = make_float4(0.f, 0.f, 0.f, 0.f);
        if (node < N) v = __ldg(&reinterpret_cast<const float4*>(g_agg)[(long long)node * 16 + kq]);
        float vv[4] = {v.x, v.y, v.z, v.w};
#pragma unroll
        for (int j = 0; j < 4; j++) {
            int jj = (j + kq) & 3;
            sA[(4 * kq + jj) * APAD + n] = vv[jj];
        }
    }
    __syncthreads();

    int n0 = ty * 4, c0 = tx * 4;

    unsigned long long acc[4][2];   // [node i][col pair j2], f32x2 packed
    {
        float4 bv = __ldg(&reinterpret_cast<const float4*>(b1)[tx]);
        unsigned long long b01 = pack2(bv.x, bv.y), b23 = pack2(bv.z, bv.w);
#pragma unroll
        for (int i = 0; i < 4; i++) { acc[i][0] = b01; acc[i][1] = b23; }
    }

    // ---- layer 1 ----
#pragma unroll 4
    for (int k = 0; k < KFEAT; k++) {
        float4 a = *reinterpret_cast<const float4*>(&sA[k * APAD + n0]);
        ulonglong2 w = *reinterpret_cast<const ulonglong2*>(&sW1[k * 64 + c0]);
        unsigned long long r0 = rep2(a.x), r1 = rep2(a.y), r2 = rep2(a.z), r3 = rep2(a.w);
        fma2(acc[0][0], r0, w.x); fma2(acc[0][1], r0, w.y);
        fma2(acc[1][0], r1, w.x); fma2(acc[1][1], r1, w.y);
        fma2(acc[2][0], r2, w.x); fma2(acc[2][1], r2, w.y);
        fma2(acc[3][0], r3, w.x); fma2(acc[3][1], r3, w.y);
    }
    __syncthreads();   // done reading sA before it becomes hid^T

    // softplus, write hid transposed into sA[c][n] (padded rows)
#pragma unroll
    for (int j2 = 0; j2 < 2; j2++) {
#pragma unroll
        for (int ii = 0; ii < 4; ii++) {
            int i = (ii + tx) & 3;
            float lo, hi;
            unpack2(acc[i][j2], lo, hi);
            sA[(c0 + 2 * j2)     * APAD + (n0 + i)] = softplus_f(lo);
            sA[(c0 + 2 * j2 + 1) * APAD + (n0 + i)] = softplus_f(hi);
        }
    }
    __syncthreads();

    {
        float4 bv = __ldg(&reinterpret_cast<const float4*>(b2)[tx]);
        unsigned long long b01 = pack2(bv.x, bv.y), b23 = pack2(bv.z, bv.w);
#pragma unroll
        for (int i = 0; i < 4; i++) { acc[i][0] = b01; acc[i][1] = b23; }
    }

    // ---- layer 2 ----
#pragma unroll 4
    for (int c = 0; c < KFEAT; c++) {
        float4 a = *reinterpret_cast<const float4*>(&sA[c * APAD + n0]);
        ulonglong2 w = *reinterpret_cast<const ulonglong2*>(&sW2[c * 64 + c0]);
        unsigned long long r0 = rep2(a.x), r1 = rep2(a.y), r2 = rep2(a.z), r3 = rep2(a.w);
        fma2(acc[0][0], r0, w.x); fma2(acc[0][1], r0, w.y);
        fma2(acc[1][0], r1, w.x); fma2(acc[1][1], r1, w.y);
        fma2(acc[2][0], r2, w.x); fma2(acc[2][1], r2, w.y);
        fma2(acc[3][0], r3, w.x); fma2(acc[3][1], r3, w.y);
    }

    // Store: float4 per node row
#pragma unroll
    for (int i = 0; i < 4; i++) {
        int node = base + n0 + i;
        if (node < N) {
            float o0, o1, o2, o3;
            unpack2(acc[i][0], o0, o1);
            unpack2(acc[i][1], o2, o3);
            reinterpret_cast<float4*>(out)[(long long)node * 16 + tx] =
                make_float4(o0, o1, o2, o3);
        }
    }
}

// ---------------------------------------------------------------------------
// Inputs (metadata order): h, dist, W1, b1, W2, b2, src_idx, dst_idx
// ---------------------------------------------------------------------------
extern "C" void kernel_launch(void* const* d_in, const int* in_sizes, int n_in,
                              void* d_out, int out_size) {
    const float* h    = (const float*)d_in[0];
    const float* dist = (const float*)d_in[1];
    const float* W1   = (const float*)d_in[2];
    const float* b1   = (const float*)d_in[3];
    const float* W2   = (const float*)d_in[4];
    const float* b2   = (const float*)d_in[5];
    const int*   src  = (const int*)d_in[6];
    const int*   dst  = (const int*)d_in[7];
    float* out = (float*)d_out;

    int E = in_sizes[1];            // n_edges
    int N = in_sizes[0] / KFEAT;    // n_nodes

    // 1) zero counters (g_agg fully overwritten by gather)
    zero_kernel<<<(N + 255) / 256, 256>>>(N);

    // 2) bin edges by dst, packing (dist, src) records
    bin_kernel<<<(E + 255) / 256, 256>>>(dist, src, dst, E);

    // 3) gather-accumulate per node (plain stores, no atomics)
    int gt = N * 16;
    gather_kernel<<<(gt + 255) / 256, 256>>>(h, N);

    // 3b) overflow edges (normally none) — atomics after gather
    ovf_kernel<<<128, 256>>>(h, dist, src, dst);

    // 4) MLP: tiled SGEMM with f32x2 FMA, 64 nodes per block
    int mblocks = (N + 63) / 64;
    mlp_gemm_kernel<<<mblocks, 256>>>(W1, b1, W2, b2, out, N);
}